// round 4
// baseline (speedup 1.0000x reference)
#include <cuda_runtime.h>
#include <math.h>

#define D 128
#define G 256
#define BMAX 8192
#define CHUNK 8   // nodes per warp (2 phases x 4 nodes, 8 lanes per node)

__device__ float g_w[D];        // Wp @ We[:G]
__device__ float g_c;           // bp . We[:G]
__device__ float g_accum[BMAX]; // zero at module load; combine re-zeroes after use
__device__ float g_src[BMAX];   // src-embed dot per graph

// ---------------------------------------------------------------------------
// Kernel 1: fold Wp/bp into We's graph-embed half.
// warps 0..127 -> g_w[warp]; warp 128 -> g_c.
// ---------------------------------------------------------------------------
__global__ void dgmg_precompute(const float* __restrict__ Wp,
                                const float* __restrict__ bp,
                                const float* __restrict__ We) {
    int gt   = blockIdx.x * blockDim.x + threadIdx.x;
    int gw   = gt >> 5;
    int lane = gt & 31;
    if (gw < D) {
        const float* row = Wp + (size_t)gw * G;
        float s = 0.0f;
        #pragma unroll
        for (int i = 0; i < G / 32; i++) {
            int idx = lane + 32 * i;
            s += row[idx] * We[idx];
        }
        #pragma unroll
        for (int off = 16; off > 0; off >>= 1)
            s += __shfl_xor_sync(0xffffffffu, s, off);
        if (lane == 0) g_w[gw] = s;
    } else if (gw == D) {
        float s = 0.0f;
        #pragma unroll
        for (int i = 0; i < G / 32; i++) {
            int idx = lane + 32 * i;
            s += bp[idx] * We[idx];
        }
        #pragma unroll
        for (int off = 16; off > 0; off >>= 1)
            s += __shfl_xor_sync(0xffffffffu, s, off);
        if (lane == 0) g_c = s;
    }
}

// ---------------------------------------------------------------------------
// Kernel 2: fused main pass.
//   Blocks [0, nodeBlocks):  stream hv. One warp = 8 nodes. Each lane owns
//     16 columns (4 float4) of one row; 8 lanes per node, 4 nodes per phase,
//     2 phases. All 8 row-loads per lane are front-batched (4KB/warp in
//     flight). Reduction = 3 xor-shuffle rounds per phase (1.5 SHFL/node).
//     Sorted seg_ids -> lane-0 run-length scan, ~1 atomicAdd per warp.
//   Blocks [nodeBlocks, ...): src-embed gather. One warp per graph, dot with
//     We[G:], result -> g_src[b]. Overlaps with the hv stream.
// ---------------------------------------------------------------------------
__global__ void __launch_bounds__(256)
dgmg_main(const float* __restrict__ hv,
          const float* __restrict__ Wg,
          const float* __restrict__ bg,
          const int*   __restrict__ seg,
          const float* __restrict__ We,
          const int*   __restrict__ last_idx,
          int N, int B, int nodeBlocks) {
    const int lane   = threadIdx.x & 31;
    const int warpIB = threadIdx.x >> 5;

    if (blockIdx.x >= nodeBlocks) {
        // ---- src-embed gather branch ----
        const int b = (blockIdx.x - nodeBlocks) * 8 + warpIB;
        if (b >= B) return;
        const int li = __ldg(last_idx + b);
        const float4 h  = reinterpret_cast<const float4*>(hv + (size_t)li * D)[lane];
        const float4 we = reinterpret_cast<const float4*>(We + G)[lane];
        float d = h.x * we.x + h.y * we.y + h.z * we.z + h.w * we.w;
        #pragma unroll
        for (int off = 16; off > 0; off >>= 1)
            d += __shfl_xor_sync(0xffffffffu, d, off);
        if (lane == 0) g_src[b] = d;
        return;
    }

    // ---- node streaming branch ----
    const int wid   = blockIdx.x * 8 + warpIB;
    const int start = wid * CHUNK;
    if (start >= N) return;
    const int cnt = min(CHUNK, N - start);

    const int sub = lane >> 3;        // node subgroup 0..3
    const int col = (lane & 7) * 4;   // float4 base index within row

    const float4* hv4 = reinterpret_cast<const float4*>(hv);
    const float4* Wg4 = reinterpret_cast<const float4*>(Wg);
    const float4* gw4 = reinterpret_cast<const float4*>(g_w);

    // front-batched independent loads: 8 LDG.128 per lane
    float4 r[8];
    {
        const size_t n0 = (size_t)min(start + sub,     N - 1);
        const size_t n1 = (size_t)min(start + 4 + sub, N - 1);
        #pragma unroll
        for (int j = 0; j < 4; j++) r[j]     = __ldg(hv4 + n0 * 32 + col + j);
        #pragma unroll
        for (int j = 0; j < 4; j++) r[4 + j] = __ldg(hv4 + n1 * 32 + col + j);
    }
    const int segv = __ldg(seg + min(start + (lane & 7), N - 1));

    float4 wg[4], wv[4];
    #pragma unroll
    for (int j = 0; j < 4; j++) { wg[j] = __ldg(Wg4 + col + j); wv[j] = gw4[col + j]; }

    const float bg0 = __ldg(bg);
    const float c0  = g_c;

    float cphase[2];
    #pragma unroll
    for (int p = 0; p < 2; p++) {
        float d1 = 0.0f, d2 = 0.0f;
        #pragma unroll
        for (int j = 0; j < 4; j++) {
            const float4 h = r[p * 4 + j];
            d1 += h.x * wg[j].x + h.y * wg[j].y + h.z * wg[j].z + h.w * wg[j].w;
            d2 += h.x * wv[j].x + h.y * wv[j].y + h.z * wv[j].z + h.w * wv[j].w;
        }
        // reduce across the 8 lanes of this node's subgroup
        #pragma unroll
        for (int off = 4; off > 0; off >>= 1) {
            d1 += __shfl_xor_sync(0xffffffffu, d1, off);
            d2 += __shfl_xor_sync(0xffffffffu, d2, off);
        }
        const float gate = 1.0f / (1.0f + __expf(-(d1 + bg0)));
        cphase[p] = gate * (d2 + c0);
    }

    // lane 0 collects 8 (seg, contrib) pairs and run-length aggregates
    int   cur_seg = __shfl_sync(0xffffffffu, segv, 0);
    float acc     = 0.0f;
    #pragma unroll
    for (int k = 0; k < CHUNK; k++) {
        const float ck = __shfl_sync(0xffffffffu, cphase[k >> 2], (k & 3) * 8);
        const int   sk = __shfl_sync(0xffffffffu, segv, k);
        if (lane == 0 && k < cnt) {
            if (sk != cur_seg) {
                atomicAdd(&g_accum[cur_seg], acc);
                acc = 0.0f;
                cur_seg = sk;
            }
            acc += ck;
        }
    }
    if (lane == 0) atomicAdd(&g_accum[cur_seg], acc);
}

// ---------------------------------------------------------------------------
// Kernel 3: tiny combine. One thread per graph.
// ---------------------------------------------------------------------------
__global__ void __launch_bounds__(256)
dgmg_combine(const float* __restrict__ be,
             const int*   __restrict__ a,
             float*       __restrict__ out,
             int B) {
    const int b = blockIdx.x * blockDim.x + threadIdx.x;
    if (b >= B) return;
    float logit = g_accum[b] + g_src[b] + be[0];
    g_accum[b] = 0.0f;   // reset for next replay
    float x = (a[b] != 0) ? logit : -logit;
    float ls = (x >= 0.0f) ? -log1pf(expf(-x)) : (x - log1pf(expf(x)));
    out[b] = ls;
}

// ---------------------------------------------------------------------------
extern "C" void kernel_launch(void* const* d_in, const int* in_sizes, int n_in,
                              void* d_out, int out_size) {
    const float* hv       = (const float*)d_in[0];
    const float* Wg       = (const float*)d_in[1];
    const float* bg       = (const float*)d_in[2];
    const float* Wp       = (const float*)d_in[3];
    const float* bp       = (const float*)d_in[4];
    const float* We       = (const float*)d_in[5];
    const float* be       = (const float*)d_in[6];
    const int*   seg_ids  = (const int*)d_in[7];
    const int*   last_idx = (const int*)d_in[8];
    const int*   a        = (const int*)d_in[9];
    float* out = (float*)d_out;

    const int N = in_sizes[0] / D;
    const int B = in_sizes[8];

    // K1: fold weights
    dgmg_precompute<<<17, 256>>>(Wp, bp, We);

    // K2: fused node stream + src gather
    const int nodeWarps  = (N + CHUNK - 1) / CHUNK;
    const int nodeBlocks = (nodeWarps + 7) / 8;
    const int srcBlocks  = (B + 7) / 8;
    dgmg_main<<<nodeBlocks + srcBlocks, 256>>>(hv, Wg, bg, seg_ids, We,
                                               last_idx, N, B, nodeBlocks);

    // K3: combine
    dgmg_combine<<<(B + 255) / 256, 256>>>(be, a, out, B);
}